// round 6
// baseline (speedup 1.0000x reference)
#include <cuda_runtime.h>
#include <cuda_bf16.h>
#include <cstddef>

// Enframe: x (8,2,480000) f32 -> out (8,4096,934) f32
//   out[b, c*2048 + k, t] = x[b, c, t*512 + k]
// Decompose k = 512*q + r (q in [0,4), r in [0,512)), bc = b*2+c:
//   out[bc, q*512 + r, t] = x[bc, (t+q)*512 + r]
// R3 tile (128 t x 32 r) kept; 2 t-tiles fused per block -> 1024 blocks =
// single resident wave (8 blocks/SM x 148 SM = 1184). Tile B's LDGs are
// prefetched into registers during tile A's store phase.

#define S_LEN     480000
#define T_OUT     934          // (480000 - 2048)/512 + 1
#define SLOTS     937          // max slot = 933 + 3 = 936
#define ROWS      2048         // per-bc output rows
#define R_PAD     33
#define T_TILE    128
#define SLOT_NEED 131          // 128 t + q shift (3)

__global__ __launch_bounds__(256) void enframe_kernel(const float4* __restrict__ x4,
                                                      float* __restrict__ out) {
    __shared__ float tile[SLOT_NEED * R_PAD];   // 131*33*4 = 17292 B

    const int rt   = blockIdx.x;   // 0..15  r base = rt*32
    const int tsup = blockIdx.y;   // 0..3   covers t-tiles {2*tsup, 2*tsup+1}
    const int bc   = blockIdx.z;   // 0..15
    const int tx   = threadIdx.x;  // 0..31
    const int ty   = threadIdx.y;  // 0..7

    const float4* __restrict__ xin = x4 + (size_t)bc * (S_LEN / 4);
    const int c    = tx & 7;          // float4 column: r = rt*32 + 4c + j
    const int lrow = ty * 4 + (tx >> 3);   // 0..31

    float4 v[5];

    auto do_load = [&](int tt) {
        const int tb = tt * T_TILE;
        const bool inter = (tt < 7);
#pragma unroll
        for (int p = 0; p < 5; ++p) {
            const int row = p * 32 + lrow;
            v[p] = make_float4(0.f, 0.f, 0.f, 0.f);
            if (row < SLOT_NEED) {
                const int s = tb + row;
                if (inter || s < SLOTS) v[p] = xin[(size_t)s * 128 + rt * 8 + c];
            }
        }
    };

    auto do_sts = [&]() {
#pragma unroll
        for (int p = 0; p < 5; ++p) {
            const int row = p * 32 + lrow;
            if (row < SLOT_NEED) {
                float* dst = &tile[row * R_PAD + 4 * c];
                dst[0] = v[p].x; dst[1] = v[p].y; dst[2] = v[p].z; dst[3] = v[p].w;
            }
        }
    };

    auto do_store = [&](int tt) {
        const int tb = tt * T_TILE;
        const bool inter = (tt < 7);
        const int q    = ty >> 1;
        const int half = ty & 1;
        const int t    = tb + half * 64 + 2 * tx;   // even t; pair (t, t+1)
        const int row  = half * 64 + 2 * tx + q;    // slot row for t
        const float* __restrict__ src = &tile[row * R_PAD];
        float* __restrict__ o = out + (size_t)bc * ROWS * T_OUT
                                    + (size_t)(q * 512 + rt * 32) * T_OUT + t;
        if (inter || t < T_OUT) {   // t even, T_OUT even -> pair fully valid
#pragma unroll
            for (int rl = 0; rl < 32; ++rl) {
                float2 w;
                w.x = src[rl];            // tile[row][rl]
                w.y = src[R_PAD + rl];    // tile[row+1][rl]  (slot s+1 -> t+1)
                *(float2*)o = w;          // STG.64, 8B-aligned (934*4 % 8 == 0)
                o += T_OUT;
            }
        }
    };

    const int tt0 = tsup * 2;
    const int tt1 = tt0 + 1;

    do_load(tt0);
    do_sts();
    __syncthreads();

    do_load(tt1);        // prefetch: LDGs fly while tile0 is stored
    do_store(tt0);
    __syncthreads();     // WAR: all tile0 reads complete before overwrite

    do_sts();
    __syncthreads();
    do_store(tt1);
}

extern "C" void kernel_launch(void* const* d_in, const int* in_sizes, int n_in,
                              void* d_out, int out_size) {
    const float4* x = (const float4*)d_in[0];
    float* out = (float*)d_out;

    dim3 block(32, 8, 1);
    dim3 grid(16, 4, 16);   // (r tiles of 32, t super-tiles of 256, bc)
    enframe_kernel<<<grid, block>>>(x, out);
}